// round 15
// baseline (speedup 1.0000x reference)
#include <cuda_runtime.h>
#include <cuda_bf16.h>
#include <math.h>
#include <cstdint>

// ---------------------------------------------------------------------------
// ClusterAttn: b=1, D=32, H=128, W=128, C=96, P=4, FEAD=64, K=64
//  init_all : zero small accumulators (k45 is ncu's 4th launch)
//  k1_mma : dwc stage1 via mma.sync bf16: Y[NP,27] = X[NP,96]@W[96,27]
//  k2     : 27-tap gather -> fea (raw) + column sum-of-squares
//  k45    : FUSED soft-assign + newcacc (16-token tiles, grid 512)
//  k5b    : normalize -> kv -> fold M/d
//  kAttn  : logits -> softmax -> attn@v -> scatter to o1
//  k9_mma : upc conv as GEMM, 256 threads, warp-parallel N-split
// ---------------------------------------------------------------------------

#define DD 32
#define HH 128
#define WW 128
#define NP (DD*HH*WW)      // 524288 voxels
#define CC 96
#define NT 8192            // tokens
#define FE 64              // FEAD
#define KK 64              // clusters

// ------------------------- scratch (device globals) -------------------------
__device__ __align__(256) __nv_bfloat16 g_yb[27*NP];   // 28.3 MB
__device__ __align__(256) float g_fea[NT*FE];          // raw (un-normalized)
__device__ __align__(256) float g_o1[NP];
__device__ __align__(256) float g_ssq[FE];
__device__ __align__(256) float g_colsum[KK];
__device__ __align__(256) float g_newcacc[KK*FE];
__device__ __align__(256) float g_v[KK*FE];
__device__ __align__(256) float g_M[KK*FE];
__device__ __align__(256) float g_d[KK];

// ------------------------- warp-level bf16 MMA -------------------------------
__device__ __forceinline__ void mma16816(float* c,
        uint32_t a0, uint32_t a1, uint32_t a2, uint32_t a3,
        uint32_t b0, uint32_t b1) {
    asm volatile(
        "mma.sync.aligned.m16n8k16.row.col.f32.bf16.bf16.f32 "
        "{%0,%1,%2,%3}, {%4,%5,%6,%7}, {%8,%9}, {%0,%1,%2,%3};"
        : "+f"(c[0]), "+f"(c[1]), "+f"(c[2]), "+f"(c[3])
        : "r"(a0), "r"(a1), "r"(a2), "r"(a3), "r"(b0), "r"(b1));
}

// ------------------------- single init kernel -------------------------------
__global__ void init_all() {
    int t = threadIdx.x;
    if (t < FE) g_ssq[t] = 0.f;
    if (t < KK) g_colsum[t] = 0.f;
    for (int i = t; i < KK*FE; i += 256) g_newcacc[i] = 0.f;
}

// ------------------------- k1: dwc stage1 via mma.sync -----------------------
#define K1_VB 512
__global__ __launch_bounds__(128) void k1_mma(const float* __restrict__ x,
                                              const float* __restrict__ dwc_w) {
    __shared__ uint32_t ws[48*40];       // B: bf16x2 (W[2m][n], W[2m+1][n])
    __shared__ uint32_t xs[128*52];      // A: bf16x2 (x[v][2m], x[v][2m+1])
    __shared__ float    os[27*128];      // D transpose buffer
    int tid = threadIdx.x, lane = tid & 31, wid = tid >> 5;
    int g = lane >> 2, tg = lane & 3;

    for (int i = tid; i < 48*32; i += 128) {
        int m = i >> 5, n = i & 31;
        float w0 = 0.f, w1 = 0.f;
        if (n < 27) { w0 = dwc_w[(2*m)*27 + n]; w1 = dwc_w[(2*m+1)*27 + n]; }
        __nv_bfloat162 h = __floats2bfloat162_rn(w0, w1);
        ws[m*40 + n] = *reinterpret_cast<uint32_t*>(&h);
    }

    int vbase = blockIdx.x * K1_VB;
#pragma unroll 1
    for (int sub = 0; sub < 4; sub++) {
        int v0 = vbase + sub*128;
        __syncthreads();
        const float4* src = reinterpret_cast<const float4*>(x + (size_t)v0*CC);
#pragma unroll
        for (int it = 0; it < 24; it++) {
            int e = it*128 + tid;
            float4 val = src[e];
            int v = e / 24, c4 = e % 24;
            __nv_bfloat162 h0 = __floats2bfloat162_rn(val.x, val.y);
            __nv_bfloat162 h1 = __floats2bfloat162_rn(val.z, val.w);
            xs[v*52 + c4*2]     = *reinterpret_cast<uint32_t*>(&h0);
            xs[v*52 + c4*2 + 1] = *reinterpret_cast<uint32_t*>(&h1);
        }
        __syncthreads();

        float c[2][4][4];
#pragma unroll
        for (int tl = 0; tl < 2; tl++)
#pragma unroll
            for (int nt = 0; nt < 4; nt++)
#pragma unroll
                for (int j = 0; j < 4; j++) c[tl][nt][j] = 0.f;

#pragma unroll
        for (int tl = 0; tl < 2; tl++) {
            int vloc = wid*32 + tl*16 + g;
#pragma unroll
            for (int ks = 0; ks < 6; ks++) {
                int m0 = ks*8 + tg;
                uint32_t a0 = xs[vloc*52 + m0];
                uint32_t a1 = xs[(vloc+8)*52 + m0];
                uint32_t a2 = xs[vloc*52 + m0 + 4];
                uint32_t a3 = xs[(vloc+8)*52 + m0 + 4];
#pragma unroll
                for (int nt = 0; nt < 4; nt++) {
                    uint32_t b0 = ws[(ks*8 + tg)*40     + nt*8 + g];
                    uint32_t b1 = ws[(ks*8 + tg + 4)*40 + nt*8 + g];
                    mma16816(c[tl][nt], a0, a1, a2, a3, b0, b1);
                }
            }
        }
#pragma unroll
        for (int tl = 0; tl < 2; tl++) {
            int row = wid*32 + tl*16 + g;
#pragma unroll
            for (int nt = 0; nt < 4; nt++) {
                int col = nt*8 + tg*2;
                if (col < 27) {
                    os[col*128 + row]     = c[tl][nt][0];
                    os[col*128 + row + 8] = c[tl][nt][2];
                }
                if (col + 1 < 27) {
                    os[(col+1)*128 + row]     = c[tl][nt][1];
                    os[(col+1)*128 + row + 8] = c[tl][nt][3];
                }
            }
        }
        __syncthreads();
        for (int i = tid; i < 27*64; i += 128) {
            int t = i >> 6, p = i & 63;
            __nv_bfloat162 h = __floats2bfloat162_rn(os[t*128 + 2*p],
                                                     os[t*128 + 2*p + 1]);
            *reinterpret_cast<uint32_t*>(
                reinterpret_cast<char*>(g_yb) + ((size_t)t*NP + v0 + 2*p)*2) =
                *reinterpret_cast<uint32_t*>(&h);
        }
    }
}

// ------------------------- k2: gather + fea (raw) + ssq ----------------------
__global__ __launch_bounds__(256) void k2_gather(const float* __restrict__ dwc_b) {
    __shared__ float ssq_s[FE];
    int tid = threadIdx.x;
    if (tid < FE) ssq_s[tid] = 0.f;
    __syncthreads();

    int p = blockIdx.x*256 + tid;
    int z = p >> 14, y = (p >> 7) & 127, xx = p & 127;

    float v = dwc_b[0];
#pragma unroll
    for (int kz = 0; kz < 3; kz++) {
        int zz = z + kz - 1; if ((unsigned)zz >= DD) continue;
#pragma unroll
        for (int ky = 0; ky < 3; ky++) {
            int yy = y + ky - 1; if ((unsigned)yy >= HH) continue;
#pragma unroll
            for (int kx = 0; kx < 3; kx++) {
                int xc = xx + kx - 1; if ((unsigned)xc >= WW) continue;
                int t = kz*9 + ky*3 + kx;
                v += __bfloat162float(g_yb[(size_t)t*NP + (zz*HH + yy)*WW + xc]);
            }
        }
    }
    int n = ((z >> 2) << 10) | ((y >> 2) << 5) | (xx >> 2);
    int f = ((z & 3) << 4) | ((y & 3) << 2) | (xx & 3);
    g_fea[n*FE + f] = v;
    atomicAdd(&ssq_s[f], v*v);
    __syncthreads();
    if (tid < FE) atomicAdd(&g_ssq[tid], ssq_s[tid]);
}

// ------------------------- k45: FUSED logits+exp+colsum+newcacc -------------
// 16-token tiles, grid 512 (3.5 blocks/SM). Phase 1: thread = (token, clu quad).
// Phase 2: 4x4 outer-product over the 16-token tile, atomics out.
__global__ __launch_bounds__(256) void k45_assign(const float* __restrict__ cen) {
    __shared__ float inv_s[FE];
    __shared__ float cenT_s[FE*68];      // [k][c], pitch 68, pre-scaled by inv
    __shared__ float fea_s[16*68];       // [tok][k]
    __shared__ float e_s[16*68];         // [tok][c]
    __shared__ float cs_s[KK];
    int tid = threadIdx.x;
    if (tid < FE) inv_s[tid] = 1.f / fmaxf(sqrtf(g_ssq[tid]), 1e-12f);
    if (tid < KK) cs_s[tid] = 0.f;
    __syncthreads();
    for (int i = tid; i < KK*FE; i += 256) {   // cen[c][k] -> cenT_s[k][c]*inv
        int c = i >> 6, k = i & 63;
        cenT_s[k*68 + c] = cen[i] * inv_s[k];
    }
    int n0 = blockIdx.x * 16;
    for (int i = tid; i < 16*FE; i += 256) {
        int r = i >> 6, k = i & 63;
        fea_s[r*68 + k] = g_fea[(n0 + r)*FE + k];
    }
    __syncthreads();

    // ---- phase 1: logits + exp (thread = 1 token x 4 clusters) ----
    {
        int tk = tid >> 4;                     // token 0..15
        int c0 = (tid & 15) * 4;               // cluster quad
        float ax=0, ay=0, az=0, aw=0;
#pragma unroll 8
        for (int k = 0; k < FE; k++) {
            float f0 = fea_s[tk*68 + k];
            float4 cv = *reinterpret_cast<const float4*>(&cenT_s[k*68 + c0]);
            ax += f0*cv.x; ay += f0*cv.y; az += f0*cv.z; aw += f0*cv.w;
        }
        float ex = __expf(ax), ey = __expf(ay), ez = __expf(az), ew = __expf(aw);
        *reinterpret_cast<float4*>(&e_s[tk*68 + c0]) = make_float4(ex, ey, ez, ew);
        atomicAdd(&cs_s[c0+0], ex);
        atomicAdd(&cs_s[c0+1], ey);
        atomicAdd(&cs_s[c0+2], ez);
        atomicAdd(&cs_s[c0+3], ew);
    }
    __syncthreads();

    // ---- phase 2: newcacc outer-product ----
    {
        int c0 = (tid >> 4) * 4;
        int f0 = (tid & 15) * 4;
        float a00=0,a01=0,a02=0,a03=0, a10=0,a11=0,a12=0,a13=0;
        float a20=0,a21=0,a22=0,a23=0, a30=0,a31=0,a32=0,a33=0;
#pragma unroll
        for (int n = 0; n < 16; n++) {
            float4 e4 = *reinterpret_cast<const float4*>(&e_s[n*68 + c0]);
            float4 f4 = *reinterpret_cast<const float4*>(&fea_s[n*68 + f0]);
            a00 += e4.x*f4.x; a01 += e4.x*f4.y; a02 += e4.x*f4.z; a03 += e4.x*f4.w;
            a10 += e4.y*f4.x; a11 += e4.y*f4.y; a12 += e4.y*f4.z; a13 += e4.y*f4.w;
            a20 += e4.z*f4.x; a21 += e4.z*f4.y; a22 += e4.z*f4.z; a23 += e4.z*f4.w;
            a30 += e4.w*f4.x; a31 += e4.w*f4.y; a32 += e4.w*f4.z; a33 += e4.w*f4.w;
        }
        float* base = g_newcacc + c0*FE + f0;
        atomicAdd(base+0,      a00); atomicAdd(base+1,      a01);
        atomicAdd(base+2,      a02); atomicAdd(base+3,      a03);
        atomicAdd(base+FE+0,   a10); atomicAdd(base+FE+1,   a11);
        atomicAdd(base+FE+2,   a12); atomicAdd(base+FE+3,   a13);
        atomicAdd(base+2*FE+0, a20); atomicAdd(base+2*FE+1, a21);
        atomicAdd(base+2*FE+2, a22); atomicAdd(base+2*FE+3, a23);
        atomicAdd(base+3*FE+0, a30); atomicAdd(base+3*FE+1, a31);
        atomicAdd(base+3*FE+2, a32); atomicAdd(base+3*FE+3, a33);
    }
    if (tid < KK) atomicAdd(&g_colsum[tid], cs_s[tid]);
}

// ------------------------- k5b: normalize + kv + M/d fold -------------------
__global__ __launch_bounds__(128) void k5b_kv(const float* __restrict__ kv_w,
                                              const float* __restrict__ kv_b,
                                              const float* __restrict__ qw,
                                              const float* __restrict__ qb) {
    int c = blockIdx.x;                          // grid 64
    int tid = threadIdx.x;
    __shared__ float nc_s[FE], k_s[FE];
    if (tid < FE) {
        float inv = 1.f / fmaxf(sqrtf(g_ssq[tid]), 1e-12f);
        nc_s[tid] = g_newcacc[c*FE + tid] * inv / g_colsum[c];
    }
    __syncthreads();
    {                                            // kv projection
        float a = kv_b[tid];
        const float* wr = kv_w + tid*FE;
#pragma unroll
        for (int f = 0; f < FE; f++) a += nc_s[f] * wr[f];
        if (tid < 64) k_s[tid] = a;
        else          g_v[c*FE + (tid - 64)] = a;
    }
    __syncthreads();
    if (tid < 64) {                              // M fold
        float m = 0.f;
#pragma unroll 8
        for (int j = 0; j < FE; j++) m += k_s[j] * qw[j*FE + tid];
        float inv = 1.f / fmaxf(sqrtf(g_ssq[tid]), 1e-12f);
        g_M[c*FE + tid] = 0.125f * inv * m;
    } else if (tid == 64) {                      // d fold
        float dd = 0.f;
        for (int j = 0; j < FE; j++) dd += qb[j] * k_s[j];
        g_d[c] = 0.125f * dd;
    }
}

// ------------------------- kAttn: logits -> softmax -> @v -> scatter --------
__global__ __launch_bounds__(64) void kAttn() {
    __shared__ float M_s[KK*FE];                  // 16 KB
    __shared__ float v_s[KK*FE];                  // 16 KB
    __shared__ float d_s[KK];
    int tid = threadIdx.x;
    for (int i = tid; i < KK*FE; i += 64) { M_s[i] = g_M[i]; v_s[i] = g_v[i]; }
    if (tid < KK) d_s[tid] = g_d[tid];
    __syncthreads();

    int n = blockIdx.x*64 + tid;                  // token id, grid NT/64
    float fr[FE];
    const float4* frp = reinterpret_cast<const float4*>(g_fea + n*FE);
#pragma unroll
    for (int f4 = 0; f4 < 16; f4++) {
        float4 v = frp[f4];
        fr[f4*4] = v.x; fr[f4*4+1] = v.y; fr[f4*4+2] = v.z; fr[f4*4+3] = v.w;
    }
    float a[KK];
    float mx = -1e30f;
#pragma unroll 4
    for (int c = 0; c < KK; c++) {
        const float4* mr = reinterpret_cast<const float4*>(M_s + c*FE);
        float l = d_s[c];
#pragma unroll
        for (int f4 = 0; f4 < 16; f4++) {
            float4 w = mr[f4];
            l += fr[f4*4]*w.x + fr[f4*4+1]*w.y + fr[f4*4+2]*w.z + fr[f4*4+3]*w.w;
        }
        a[c] = l;
        mx = fmaxf(mx, l);
    }
    float s = 0.f;
#pragma unroll
    for (int c = 0; c < KK; c++) { a[c] = __expf(a[c] - mx); s += a[c]; }
    float si = 1.f / s;

    float acc[FE];
#pragma unroll
    for (int f = 0; f < FE; f++) acc[f] = 0.f;
#pragma unroll 4
    for (int c = 0; c < KK; c++) {
        float ac = a[c] * si;
        const float4* vr = reinterpret_cast<const float4*>(v_s + c*FE);
#pragma unroll
        for (int f4 = 0; f4 < 16; f4++) {
            float4 v = vr[f4];
            acc[f4*4]   += ac*v.x; acc[f4*4+1] += ac*v.y;
            acc[f4*4+2] += ac*v.z; acc[f4*4+3] += ac*v.w;
        }
    }
    int xb = n & 31, yb = (n >> 5) & 31, zb = n >> 10;
#pragma unroll
    for (int f4 = 0; f4 < 16; f4++) {
        int pz = f4 >> 2, py = f4 & 3;
        int p = ((zb*4 + pz)*HH + (yb*4 + py))*WW + xb*4;
        *reinterpret_cast<float4*>(g_o1 + p) =
            make_float4(acc[f4*4], acc[f4*4+1], acc[f4*4+2], acc[f4*4+3]);
    }
}

// ------------------------- k9: upc conv as GEMM + residual ------------------
// 256 threads / 128 voxels (one (z,y) row). Warp-parallel N-split: warps 0-3
// compute channels 0-47, warps 4-7 channels 48-95 for the SAME voxels.
// Halves register pressure (c[2][6][4]) vs the 128-thread version.
__global__ __launch_bounds__(256) void k9_mma(const float* __restrict__ x,
                                              const float* __restrict__ uw,
                                              const float* __restrict__ ub,
                                              float* __restrict__ out) {
    __shared__ float    os[9*132];       // o1 window rows (halo + zero pad)
    __shared__ uint32_t as[128*20];      // A: bf16x2 (tap 2m, 2m+1), pitch 20
    __shared__ uint32_t ws[16*104];      // B: bf16x2 (W[2m][n], W[2m+1][n])
    __shared__ float    bias_s[CC];
    int tid = threadIdx.x, lane = tid & 31, wid = tid >> 5;
    int g = lane >> 2, tg = lane & 3;

    for (int i = tid; i < 16*96; i += 256) {
        int m = i / 96, n = i % 96;
        int t0 = 2*m, t1 = 2*m + 1;
        float w0 = (t0 < 27) ? uw[n*27 + t0] : 0.f;
        float w1 = (t1 < 27) ? uw[n*27 + t1] : 0.f;
        __nv_bfloat162 h = __floats2bfloat162_rn(w0, w1);
        ws[m*104 + n] = *reinterpret_cast<uint32_t*>(&h);
    }
    if (tid < CC) bias_s[tid] = ub[tid];

    int z = blockIdx.x >> 7, y = blockIdx.x & 127;
    int v0 = blockIdx.x * 128;

    for (int i = tid; i < 9*130; i += 256) {
        int row = i / 130, col = i % 130;
        int gz = z + row/3 - 1, gy = y + row%3 - 1, gx = col - 1;
        float v = 0.f;
        if ((unsigned)gz < DD && (unsigned)gy < HH && (unsigned)gx < WW)
            v = g_o1[(gz*HH + gy)*WW + gx];
        os[row*132 + col] = v;
    }
    __syncthreads();

    // A build: 256 threads, each builds 8 of the 16 bf16x2 taps for one voxel
    {
        int v = tid & 127;
        int mbase = (tid >> 7) * 8;
#pragma unroll
        for (int mm = 0; mm < 8; mm++) {
            int m = mbase + mm;
            int t0 = 2*m, t1 = 2*m + 1;
            float a0 = 0.f, a1 = 0.f;
            if (t0 < 27) a0 = os[(t0/9*3 + (t0%9)/3)*132 + v + t0%3];
            if (t1 < 27) a1 = os[(t1/9*3 + (t1%9)/3)*132 + v + t1%3];
            __nv_bfloat162 h = __floats2bfloat162_rn(a0, a1);
            as[v*20 + m] = *reinterpret_cast<uint32_t*>(&h);
        }
    }
    __syncthreads();

    int vw = wid & 3;           // voxel-warp: rows vw*32..vw*32+31
    int nh = wid >> 2;          // N-half: channels nh*48..nh*48+47

    float c[2][6][4];
#pragma unroll
    for (int tl = 0; tl < 2; tl++)
#pragma unroll
        for (int nt = 0; nt < 6; nt++)
#pragma unroll
            for (int j = 0; j < 4; j++) c[tl][nt][j] = 0.f;

#pragma unroll
    for (int tl = 0; tl < 2; tl++) {
        int vloc = vw*32 + tl*16 + g;
#pragma unroll
        for (int ks = 0; ks < 2; ks++) {
            int m0 = ks*8 + tg;
            uint32_t a0 = as[vloc*20 + m0];
            uint32_t a1 = as[(vloc+8)*20 + m0];
            uint32_t a2 = as[vloc*20 + m0 + 4];
            uint32_t a3 = as[(vloc+8)*20 + m0 + 4];
#pragma unroll
            for (int nt = 0; nt < 6; nt++) {
                int ntg = nh*6 + nt;
                uint32_t b0 = ws[(ks*8 + tg)*104     + ntg*8 + g];
                uint32_t b1 = ws[(ks*8 + tg + 4)*104 + ntg*8 + g];
                mma16816(c[tl][nt], a0, a1, a2, a3, b0, b1);
            }
        }
    }

#pragma unroll
    for (int tl = 0; tl < 2; tl++) {
        int r0 = vw*32 + tl*16 + g;
#pragma unroll
        for (int nt = 0; nt < 6; nt++) {
            int n = (nh*6 + nt)*8 + tg*2;
            float b0 = bias_s[n], b1 = bias_s[n+1];
            {
                size_t idx = (size_t)(v0 + r0)*CC + n;
                float2 xv = *reinterpret_cast<const float2*>(x + idx);
                *reinterpret_cast<float2*>(out + idx) =
                    make_float2(xv.x + b0 + c[tl][nt][0],
                                xv.y + b1 + c[tl][nt][1]);
            }
            {
                size_t idx = (size_t)(v0 + r0 + 8)*CC + n;
                float2 xv = *reinterpret_cast<const float2*>(x + idx);
                *reinterpret_cast<float2*>(out + idx) =
                    make_float2(xv.x + b0 + c[tl][nt][2],
                                xv.y + b1 + c[tl][nt][3]);
            }
        }
    }
}

// ------------------------- launch --------------------------------------------
extern "C" void kernel_launch(void* const* d_in, const int* in_sizes, int n_in,
                              void* d_out, int out_size) {
    const float* x     = (const float*)d_in[0];
    const float* cen   = (const float*)d_in[1];
    const float* dwc_w = (const float*)d_in[2];
    const float* dwc_b = (const float*)d_in[3];
    const float* upc_w = (const float*)d_in[4];
    const float* upc_b = (const float*)d_in[5];
    const float* q_w   = (const float*)d_in[6];
    const float* q_b   = (const float*)d_in[7];
    const float* kv_w  = (const float*)d_in[8];
    const float* kv_b  = (const float*)d_in[9];
    float* out = (float*)d_out;

    init_all  <<<1, 256>>>();
    k1_mma    <<<NP/K1_VB, 128>>>(x, dwc_w);
    k2_gather <<<NP/256, 256>>>(dwc_b);
    k45_assign<<<NT/16, 256>>>(cen);            // 4th launch -> ncu profiles this
    k5b_kv    <<<KK, 128>>>(kv_w, kv_b, q_w, q_b);
    kAttn     <<<NT/64, 64>>>();
    k9_mma    <<<NP/128, 256>>>(x, upc_w, upc_b, out);
}

// round 16
// speedup vs baseline: 1.1345x; 1.1345x over previous
#include <cuda_runtime.h>
#include <cuda_bf16.h>
#include <math.h>
#include <cstdint>

// ---------------------------------------------------------------------------
// ClusterAttn: b=1, D=32, H=128, W=128, C=96, P=4, FEAD=64, K=64
//  init_all : zero small accumulators (k45 is ncu's 4th launch)
//  k1_mma : dwc stage1 via mma.sync bf16: Y[NP,27] = X[NP,96]@W[96,27]
//  k2     : 27-tap gather (constant-offset addressing) + fea + ssq
//  k45    : FUSED soft-assign + newcacc (32-token tiles, grid 256) [R13 form]
//  k5b    : normalize -> kv -> fold M/d
//  kAttn  : logits -> softmax -> attn@v -> scatter to o1
//  k9_mma : upc conv as GEMM via mma.sync (single-pass 128-thr)    [R13 form]
// ---------------------------------------------------------------------------

#define DD 32
#define HH 128
#define WW 128
#define NP (DD*HH*WW)      // 524288 voxels
#define CC 96
#define NT 8192            // tokens
#define FE 64              // FEAD
#define KK 64              // clusters

// ------------------------- scratch (device globals) -------------------------
__device__ __align__(256) __nv_bfloat16 g_yb[27*NP];   // 28.3 MB
__device__ __align__(256) float g_fea[NT*FE];          // raw (un-normalized)
__device__ __align__(256) float g_o1[NP];
__device__ __align__(256) float g_ssq[FE];
__device__ __align__(256) float g_colsum[KK];
__device__ __align__(256) float g_newcacc[KK*FE];
__device__ __align__(256) float g_v[KK*FE];
__device__ __align__(256) float g_M[KK*FE];
__device__ __align__(256) float g_d[KK];

// ------------------------- warp-level bf16 MMA -------------------------------
__device__ __forceinline__ void mma16816(float* c,
        uint32_t a0, uint32_t a1, uint32_t a2, uint32_t a3,
        uint32_t b0, uint32_t b1) {
    asm volatile(
        "mma.sync.aligned.m16n8k16.row.col.f32.bf16.bf16.f32 "
        "{%0,%1,%2,%3}, {%4,%5,%6,%7}, {%8,%9}, {%0,%1,%2,%3};"
        : "+f"(c[0]), "+f"(c[1]), "+f"(c[2]), "+f"(c[3])
        : "r"(a0), "r"(a1), "r"(a2), "r"(a3), "r"(b0), "r"(b1));
}

// ------------------------- single init kernel -------------------------------
__global__ void init_all() {
    int t = threadIdx.x;
    if (t < FE) g_ssq[t] = 0.f;
    if (t < KK) g_colsum[t] = 0.f;
    for (int i = t; i < KK*FE; i += 256) g_newcacc[i] = 0.f;
}

// ------------------------- k1: dwc stage1 via mma.sync -----------------------
#define K1_VB 512
__global__ __launch_bounds__(128) void k1_mma(const float* __restrict__ x,
                                              const float* __restrict__ dwc_w) {
    __shared__ uint32_t ws[48*40];       // B: bf16x2 (W[2m][n], W[2m+1][n])
    __shared__ uint32_t xs[128*52];      // A: bf16x2 (x[v][2m], x[v][2m+1])
    __shared__ float    os[27*128];      // D transpose buffer
    int tid = threadIdx.x, lane = tid & 31, wid = tid >> 5;
    int g = lane >> 2, tg = lane & 3;

    for (int i = tid; i < 48*32; i += 128) {
        int m = i >> 5, n = i & 31;
        float w0 = 0.f, w1 = 0.f;
        if (n < 27) { w0 = dwc_w[(2*m)*27 + n]; w1 = dwc_w[(2*m+1)*27 + n]; }
        __nv_bfloat162 h = __floats2bfloat162_rn(w0, w1);
        ws[m*40 + n] = *reinterpret_cast<uint32_t*>(&h);
    }

    int vbase = blockIdx.x * K1_VB;
#pragma unroll 1
    for (int sub = 0; sub < 4; sub++) {
        int v0 = vbase + sub*128;
        __syncthreads();
        const float4* src = reinterpret_cast<const float4*>(x + (size_t)v0*CC);
#pragma unroll
        for (int it = 0; it < 24; it++) {
            int e = it*128 + tid;
            float4 val = src[e];
            int v = e / 24, c4 = e % 24;
            __nv_bfloat162 h0 = __floats2bfloat162_rn(val.x, val.y);
            __nv_bfloat162 h1 = __floats2bfloat162_rn(val.z, val.w);
            xs[v*52 + c4*2]     = *reinterpret_cast<uint32_t*>(&h0);
            xs[v*52 + c4*2 + 1] = *reinterpret_cast<uint32_t*>(&h1);
        }
        __syncthreads();

        float c[2][4][4];
#pragma unroll
        for (int tl = 0; tl < 2; tl++)
#pragma unroll
            for (int nt = 0; nt < 4; nt++)
#pragma unroll
                for (int j = 0; j < 4; j++) c[tl][nt][j] = 0.f;

#pragma unroll
        for (int tl = 0; tl < 2; tl++) {
            int vloc = wid*32 + tl*16 + g;
#pragma unroll
            for (int ks = 0; ks < 6; ks++) {
                int m0 = ks*8 + tg;
                uint32_t a0 = xs[vloc*52 + m0];
                uint32_t a1 = xs[(vloc+8)*52 + m0];
                uint32_t a2 = xs[vloc*52 + m0 + 4];
                uint32_t a3 = xs[(vloc+8)*52 + m0 + 4];
#pragma unroll
                for (int nt = 0; nt < 4; nt++) {
                    uint32_t b0 = ws[(ks*8 + tg)*40     + nt*8 + g];
                    uint32_t b1 = ws[(ks*8 + tg + 4)*40 + nt*8 + g];
                    mma16816(c[tl][nt], a0, a1, a2, a3, b0, b1);
                }
            }
        }
#pragma unroll
        for (int tl = 0; tl < 2; tl++) {
            int row = wid*32 + tl*16 + g;
#pragma unroll
            for (int nt = 0; nt < 4; nt++) {
                int col = nt*8 + tg*2;
                if (col < 27) {
                    os[col*128 + row]     = c[tl][nt][0];
                    os[col*128 + row + 8] = c[tl][nt][2];
                }
                if (col + 1 < 27) {
                    os[(col+1)*128 + row]     = c[tl][nt][1];
                    os[(col+1)*128 + row + 8] = c[tl][nt][3];
                }
            }
        }
        __syncthreads();
        for (int i = tid; i < 27*64; i += 128) {
            int t = i >> 6, p = i & 63;
            __nv_bfloat162 h = __floats2bfloat162_rn(os[t*128 + 2*p],
                                                     os[t*128 + 2*p + 1]);
            *reinterpret_cast<uint32_t*>(
                reinterpret_cast<char*>(g_yb) + ((size_t)t*NP + v0 + 2*p)*2) =
                *reinterpret_cast<uint32_t*>(&h);
        }
    }
}

// ------------------------- k2: gather + fea (raw) + ssq ----------------------
// All 27 tap addresses are p + compile-time constant:
//   addr(kz,ky,kx) = (kz*9+ky*3+kx)*NP + p + (kz-1)*16384 + (ky-1)*128 + (kx-1)
// Row-level (zz,yy) bounds checks; only kx=0/2 need x-edge predicates.
__global__ __launch_bounds__(256) void k2_gather(const float* __restrict__ dwc_b) {
    __shared__ float ssq_s[FE];
    int tid = threadIdx.x;
    if (tid < FE) ssq_s[tid] = 0.f;
    __syncthreads();

    int p = blockIdx.x*256 + tid;
    int z = p >> 14, y = (p >> 7) & 127, xx = p & 127;

    float v = dwc_b[0];
    const __nv_bfloat16* yb = g_yb;
    bool xlo = (xx >= 1), xhi = (xx < WW - 1);
#pragma unroll
    for (int kz = 0; kz < 3; kz++) {
        int zz = z + kz - 1; if ((unsigned)zz >= DD) continue;
#pragma unroll
        for (int ky = 0; ky < 3; ky++) {
            int yy = y + ky - 1; if ((unsigned)yy >= HH) continue;
            int A = p + (kz*9 + ky*3)*NP + (kz - 1)*16384 + (ky - 1)*128 - 1;
            if (xlo) v += __bfloat162float(yb[A]);
            v += __bfloat162float(yb[A + (NP + 1)]);
            if (xhi) v += __bfloat162float(yb[A + 2*(NP + 1)]);
        }
    }
    int n = ((z >> 2) << 10) | ((y >> 2) << 5) | (xx >> 2);
    int f = ((z & 3) << 4) | ((y & 3) << 2) | (xx & 3);
    g_fea[n*FE + f] = v;
    atomicAdd(&ssq_s[f], v*v);
    __syncthreads();
    if (tid < FE) atomicAdd(&g_ssq[tid], ssq_s[tid]);
}

// ------------------------- k45: FUSED logits+exp+colsum+newcacc (R13) -------
__global__ __launch_bounds__(256) void k45_assign(const float* __restrict__ cen) {
    __shared__ float inv_s[FE];
    __shared__ float cenT_s[FE*68];      // [k][c], pitch 68, pre-scaled by inv
    __shared__ float fea_s[32*68];       // [tok][k]
    __shared__ float e_s[32*68];         // [tok][c]
    __shared__ float cs_s[KK];
    int tid = threadIdx.x;
    if (tid < FE) inv_s[tid] = 1.f / fmaxf(sqrtf(g_ssq[tid]), 1e-12f);
    if (tid < KK) cs_s[tid] = 0.f;
    __syncthreads();
    for (int i = tid; i < KK*FE; i += 256) {   // cen[c][k] -> cenT_s[k][c]*inv
        int c = i >> 6, k = i & 63;
        cenT_s[k*68 + c] = cen[i] * inv_s[k];
    }
    int n0 = blockIdx.x * 32;
    for (int i = tid; i < 32*FE; i += 256) {
        int r = i >> 6, k = i & 63;
        fea_s[r*68 + k] = g_fea[(n0 + r)*FE + k];
    }
    __syncthreads();

    // ---- phase 1: logits + exp ----
    {
        int tk = (tid >> 4) * 2;               // token pair
        int c0 = (tid & 15) * 4;               // cluster quad
        float a0x=0,a0y=0,a0z=0,a0w=0, a1x=0,a1y=0,a1z=0,a1w=0;
#pragma unroll 8
        for (int k = 0; k < FE; k++) {
            float f0 = fea_s[tk*68 + k];
            float f1 = fea_s[(tk+1)*68 + k];
            float4 cv = *reinterpret_cast<const float4*>(&cenT_s[k*68 + c0]);
            a0x += f0*cv.x; a0y += f0*cv.y; a0z += f0*cv.z; a0w += f0*cv.w;
            a1x += f1*cv.x; a1y += f1*cv.y; a1z += f1*cv.z; a1w += f1*cv.w;
        }
        float e0x = __expf(a0x), e0y = __expf(a0y), e0z = __expf(a0z), e0w = __expf(a0w);
        float e1x = __expf(a1x), e1y = __expf(a1y), e1z = __expf(a1z), e1w = __expf(a1w);
        *reinterpret_cast<float4*>(&e_s[tk*68 + c0])     = make_float4(e0x, e0y, e0z, e0w);
        *reinterpret_cast<float4*>(&e_s[(tk+1)*68 + c0]) = make_float4(e1x, e1y, e1z, e1w);
        atomicAdd(&cs_s[c0+0], e0x + e1x);
        atomicAdd(&cs_s[c0+1], e0y + e1y);
        atomicAdd(&cs_s[c0+2], e0z + e1z);
        atomicAdd(&cs_s[c0+3], e0w + e1w);
    }
    __syncthreads();

    // ---- phase 2: newcacc outer-product ----
    {
        int c0 = (tid >> 4) * 4;
        int f0 = (tid & 15) * 4;
        float a00=0,a01=0,a02=0,a03=0, a10=0,a11=0,a12=0,a13=0;
        float a20=0,a21=0,a22=0,a23=0, a30=0,a31=0,a32=0,a33=0;
#pragma unroll 8
        for (int n = 0; n < 32; n++) {
            float4 e4 = *reinterpret_cast<const float4*>(&e_s[n*68 + c0]);
            float4 f4 = *reinterpret_cast<const float4*>(&fea_s[n*68 + f0]);
            a00 += e4.x*f4.x; a01 += e4.x*f4.y; a02 += e4.x*f4.z; a03 += e4.x*f4.w;
            a10 += e4.y*f4.x; a11 += e4.y*f4.y; a12 += e4.y*f4.z; a13 += e4.y*f4.w;
            a20 += e4.z*f4.x; a21 += e4.z*f4.y; a22 += e4.z*f4.z; a23 += e4.z*f4.w;
            a30 += e4.w*f4.x; a31 += e4.w*f4.y; a32 += e4.w*f4.z; a33 += e4.w*f4.w;
        }
        float* base = g_newcacc + c0*FE + f0;
        atomicAdd(base+0,      a00); atomicAdd(base+1,      a01);
        atomicAdd(base+2,      a02); atomicAdd(base+3,      a03);
        atomicAdd(base+FE+0,   a10); atomicAdd(base+FE+1,   a11);
        atomicAdd(base+FE+2,   a12); atomicAdd(base+FE+3,   a13);
        atomicAdd(base+2*FE+0, a20); atomicAdd(base+2*FE+1, a21);
        atomicAdd(base+2*FE+2, a22); atomicAdd(base+2*FE+3, a23);
        atomicAdd(base+3*FE+0, a30); atomicAdd(base+3*FE+1, a31);
        atomicAdd(base+3*FE+2, a32); atomicAdd(base+3*FE+3, a33);
    }
    if (tid < KK) atomicAdd(&g_colsum[tid], cs_s[tid]);
}

// ------------------------- k5b: normalize + kv + M/d fold -------------------
__global__ __launch_bounds__(128) void k5b_kv(const float* __restrict__ kv_w,
                                              const float* __restrict__ kv_b,
                                              const float* __restrict__ qw,
                                              const float* __restrict__ qb) {
    int c = blockIdx.x;                          // grid 64
    int tid = threadIdx.x;
    __shared__ float nc_s[FE], k_s[FE];
    if (tid < FE) {
        float inv = 1.f / fmaxf(sqrtf(g_ssq[tid]), 1e-12f);
        nc_s[tid] = g_newcacc[c*FE + tid] * inv / g_colsum[c];
    }
    __syncthreads();
    {                                            // kv projection
        float a = kv_b[tid];
        const float* wr = kv_w + tid*FE;
#pragma unroll
        for (int f = 0; f < FE; f++) a += nc_s[f] * wr[f];
        if (tid < 64) k_s[tid] = a;
        else          g_v[c*FE + (tid - 64)] = a;
    }
    __syncthreads();
    if (tid < 64) {                              // M fold
        float m = 0.f;
#pragma unroll 8
        for (int j = 0; j < FE; j++) m += k_s[j] * qw[j*FE + tid];
        float inv = 1.f / fmaxf(sqrtf(g_ssq[tid]), 1e-12f);
        g_M[c*FE + tid] = 0.125f * inv * m;
    } else if (tid == 64) {                      // d fold
        float dd = 0.f;
        for (int j = 0; j < FE; j++) dd += qb[j] * k_s[j];
        g_d[c] = 0.125f * dd;
    }
}

// ------------------------- kAttn: logits -> softmax -> @v -> scatter --------
__global__ __launch_bounds__(64) void kAttn() {
    __shared__ float M_s[KK*FE];                  // 16 KB
    __shared__ float v_s[KK*FE];                  // 16 KB
    __shared__ float d_s[KK];
    int tid = threadIdx.x;
    for (int i = tid; i < KK*FE; i += 64) { M_s[i] = g_M[i]; v_s[i] = g_v[i]; }
    if (tid < KK) d_s[tid] = g_d[tid];
    __syncthreads();

    int n = blockIdx.x*64 + tid;                  // token id, grid NT/64
    float fr[FE];
    const float4* frp = reinterpret_cast<const float4*>(g_fea + n*FE);
#pragma unroll
    for (int f4 = 0; f4 < 16; f4++) {
        float4 v = frp[f4];
        fr[f4*4] = v.x; fr[f4*4+1] = v.y; fr[f4*4+2] = v.z; fr[f4*4+3] = v.w;
    }
    float a[KK];
    float mx = -1e30f;
#pragma unroll 4
    for (int c = 0; c < KK; c++) {
        const float4* mr = reinterpret_cast<const float4*>(M_s + c*FE);
        float l = d_s[c];
#pragma unroll
        for (int f4 = 0; f4 < 16; f4++) {
            float4 w = mr[f4];
            l += fr[f4*4]*w.x + fr[f4*4+1]*w.y + fr[f4*4+2]*w.z + fr[f4*4+3]*w.w;
        }
        a[c] = l;
        mx = fmaxf(mx, l);
    }
    float s = 0.f;
#pragma unroll
    for (int c = 0; c < KK; c++) { a[c] = __expf(a[c] - mx); s += a[c]; }
    float si = 1.f / s;

    float acc[FE];
#pragma unroll
    for (int f = 0; f < FE; f++) acc[f] = 0.f;
#pragma unroll 4
    for (int c = 0; c < KK; c++) {
        float ac = a[c] * si;
        const float4* vr = reinterpret_cast<const float4*>(v_s + c*FE);
#pragma unroll
        for (int f4 = 0; f4 < 16; f4++) {
            float4 v = vr[f4];
            acc[f4*4]   += ac*v.x; acc[f4*4+1] += ac*v.y;
            acc[f4*4+2] += ac*v.z; acc[f4*4+3] += ac*v.w;
        }
    }
    int xb = n & 31, yb = (n >> 5) & 31, zb = n >> 10;
#pragma unroll
    for (int f4 = 0; f4 < 16; f4++) {
        int pz = f4 >> 2, py = f4 & 3;
        int p = ((zb*4 + pz)*HH + (yb*4 + py))*WW + xb*4;
        *reinterpret_cast<float4*>(g_o1 + p) =
            make_float4(acc[f4*4], acc[f4*4+1], acc[f4*4+2], acc[f4*4+3]);
    }
}

// ------------------------- k9: upc conv as GEMM + residual (R13/R10) --------
__global__ __launch_bounds__(128) void k9_mma(const float* __restrict__ x,
                                              const float* __restrict__ uw,
                                              const float* __restrict__ ub,
                                              float* __restrict__ out) {
    __shared__ float    os[9*132];       // o1 window rows (halo + zero pad)
    __shared__ uint32_t as[128*20];      // A: bf16x2 (tap 2m, 2m+1), pitch 20
    __shared__ uint32_t ws[16*104];      // B: bf16x2 (W[2m][n], W[2m+1][n])
    __shared__ float    bias_s[CC];
    int tid = threadIdx.x, lane = tid & 31, wid = tid >> 5;
    int g = lane >> 2, tg = lane & 3;

    for (int i = tid; i < 16*96; i += 128) {
        int m = i / 96, n = i % 96;
        int t0 = 2*m, t1 = 2*m + 1;
        float w0 = (t0 < 27) ? uw[n*27 + t0] : 0.f;
        float w1 = (t1 < 27) ? uw[n*27 + t1] : 0.f;
        __nv_bfloat162 h = __floats2bfloat162_rn(w0, w1);
        ws[m*104 + n] = *reinterpret_cast<uint32_t*>(&h);
    }
    if (tid < CC) bias_s[tid] = ub[tid];

    int z = blockIdx.x >> 7, y = blockIdx.x & 127;
    int v0 = blockIdx.x * 128;

    for (int i = tid; i < 9*130; i += 128) {
        int row = i / 130, col = i % 130;
        int gz = z + row/3 - 1, gy = y + row%3 - 1, gx = col - 1;
        float v = 0.f;
        if ((unsigned)gz < DD && (unsigned)gy < HH && (unsigned)gx < WW)
            v = g_o1[(gz*HH + gy)*WW + gx];
        os[row*132 + col] = v;
    }
    __syncthreads();

    {
        int v = tid;
#pragma unroll
        for (int m = 0; m < 16; m++) {
            int t0 = 2*m, t1 = 2*m + 1;
            float a0 = 0.f, a1 = 0.f;
            if (t0 < 27) a0 = os[(t0/9*3 + (t0%9)/3)*132 + v + t0%3];
            if (t1 < 27) a1 = os[(t1/9*3 + (t1%9)/3)*132 + v + t1%3];
            __nv_bfloat162 h = __floats2bfloat162_rn(a0, a1);
            as[v*20 + m] = *reinterpret_cast<uint32_t*>(&h);
        }
    }
    __syncthreads();

    float c[2][12][4];
#pragma unroll
    for (int tl = 0; tl < 2; tl++)
#pragma unroll
        for (int nt = 0; nt < 12; nt++)
#pragma unroll
            for (int j = 0; j < 4; j++) c[tl][nt][j] = 0.f;

#pragma unroll
    for (int tl = 0; tl < 2; tl++) {
        int vloc = wid*32 + tl*16 + g;
#pragma unroll
        for (int ks = 0; ks < 2; ks++) {
            int m0 = ks*8 + tg;
            uint32_t a0 = as[vloc*20 + m0];
            uint32_t a1 = as[(vloc+8)*20 + m0];
            uint32_t a2 = as[vloc*20 + m0 + 4];
            uint32_t a3 = as[(vloc+8)*20 + m0 + 4];
#pragma unroll
            for (int nt = 0; nt < 12; nt++) {
                uint32_t b0 = ws[(ks*8 + tg)*104     + nt*8 + g];
                uint32_t b1 = ws[(ks*8 + tg + 4)*104 + nt*8 + g];
                mma16816(c[tl][nt], a0, a1, a2, a3, b0, b1);
            }
        }
    }

#pragma unroll
    for (int tl = 0; tl < 2; tl++) {
        int r0 = wid*32 + tl*16 + g;
#pragma unroll
        for (int nt = 0; nt < 12; nt++) {
            int n = nt*8 + tg*2;
            float b0 = bias_s[n], b1 = bias_s[n+1];
            {
                size_t idx = (size_t)(v0 + r0)*CC + n;
                float2 xv = *reinterpret_cast<const float2*>(x + idx);
                *reinterpret_cast<float2*>(out + idx) =
                    make_float2(xv.x + b0 + c[tl][nt][0],
                                xv.y + b1 + c[tl][nt][1]);
            }
            {
                size_t idx = (size_t)(v0 + r0 + 8)*CC + n;
                float2 xv = *reinterpret_cast<const float2*>(x + idx);
                *reinterpret_cast<float2*>(out + idx) =
                    make_float2(xv.x + b0 + c[tl][nt][2],
                                xv.y + b1 + c[tl][nt][3]);
            }
        }
    }
}

// ------------------------- launch --------------------------------------------
extern "C" void kernel_launch(void* const* d_in, const int* in_sizes, int n_in,
                              void* d_out, int out_size) {
    const float* x     = (const float*)d_in[0];
    const float* cen   = (const float*)d_in[1];
    const float* dwc_w = (const float*)d_in[2];
    const float* dwc_b = (const float*)d_in[3];
    const float* upc_w = (const float*)d_in[4];
    const float* upc_b = (const float*)d_in[5];
    const float* q_w   = (const float*)d_in[6];
    const float* q_b   = (const float*)d_in[7];
    const float* kv_w  = (const float*)d_in[8];
    const float* kv_b  = (const float*)d_in[9];
    float* out = (float*)d_out;

    init_all  <<<1, 256>>>();
    k1_mma    <<<NP/K1_VB, 128>>>(x, dwc_w);
    k2_gather <<<NP/256, 256>>>(dwc_b);
    k45_assign<<<NT/32, 256>>>(cen);            // 4th launch -> ncu profiles this
    k5b_kv    <<<KK, 128>>>(kv_w, kv_b, q_w, q_b);
    kAttn     <<<NT/64, 64>>>();
    k9_mma    <<<NP/128, 128>>>(x, upc_w, upc_b, out);
}